// round 3
// baseline (speedup 1.0000x reference)
#include <cuda_runtime.h>
#include <cstdint>
#include <math.h>

// Problem constants
#define S_STEPS 2048   // T*P
#define NB      64     // batch
#define NI      256    // input
#define NH      128    // hidden
#define NG      512    // 4*H
#define NO      88     // output

// Scratch (static __device__ — allocation APIs are forbidden)
__device__ float g_proj[(size_t)2 * S_STEPS * NB * NG];  // 512 MB, reused by both phases
__device__ float g_tout[(size_t)S_STEPS * NB * 256];     // 128 MB
__device__ float g_pout[NB * 256];

// ---------------- helpers ----------------
__device__ __forceinline__ uint32_t smem_u32(const void* p) {
    uint32_t a;
    asm("{ .reg .u64 t; cvta.to.shared.u64 t, %1; cvt.u32.u64 %0, t; }" : "=r"(a) : "l"(p));
    return a;
}
__device__ __forceinline__ uint32_t mapa_rank(uint32_t a, uint32_t rk) {
    uint32_t r;
    asm("mapa.shared::cluster.u32 %0, %1, %2;" : "=r"(r) : "r"(a), "r"(rk));
    return r;
}
__device__ __forceinline__ void st_cluster_f32(uint32_t a, float v) {
    asm volatile("st.shared::cluster.f32 [%0], %1;" :: "r"(a), "f"(v) : "memory");
}
__device__ __forceinline__ void cluster_sync_() {
    asm volatile("barrier.cluster.arrive.aligned;" ::: "memory");
    asm volatile("barrier.cluster.wait.aligned;" ::: "memory");
}
__device__ __forceinline__ float sigmf_(float x) { return 1.0f / (1.0f + expf(-x)); }

// ---------------- projection GEMM ----------------
// out[d][s][b][p] = bias1[row]+bias2[row] + sum_k A(m,k) * W[row][k]
//   m = s*64+b (M=131072), n = d*512+p (N=1024), K=256
//   A(m,k) = A[(m&63)*sbB + (m>>6)*sbS + k]
//   p is the PERMUTED gate index: p = r*256 + t*64 + jj  <->  orig row = t*128 + r*64 + jj
__global__ void __launch_bounds__(256)
proj_gemm_kernel(const float* __restrict__ Aext, long long sbB, long long sbS,
                 const float* __restrict__ W, const float* __restrict__ bia,
                 const float* __restrict__ bib, int a_internal)
{
    __shared__ __align__(16) float As[16][132];
    __shared__ __align__(16) float Bs[16][136];

    const float* A = a_internal ? (const float*)g_tout : Aext;
    float* outp = g_proj;

    const int m0 = blockIdx.y * 128;
    const int n0 = blockIdx.x * 128;
    const int tid = threadIdx.x;
    const int tx = tid & 15;       // N micro (8 cols)
    const int ty = tid >> 4;       // M micro (8 rows)
    const int d  = n0 >> 9;

    float acc[8][8];
    #pragma unroll
    for (int i = 0; i < 8; i++)
        #pragma unroll
        for (int j = 0; j < 8; j++) acc[i][j] = 0.0f;

    for (int k0 = 0; k0 < 256; k0 += 16) {
        // load A tile: 128 rows x 16 k  (512 float4)
        #pragma unroll
        for (int q0 = 0; q0 < 2; q0++) {
            int q  = tid + q0 * 256;
            int rl = q >> 2;
            int k4 = (q & 3) * 4;
            int m  = m0 + rl;
            const float* ap = A + (long long)(m & 63) * sbB + (long long)(m >> 6) * sbS + k0 + k4;
            float4 v = *(const float4*)ap;
            As[k4 + 0][rl] = v.x; As[k4 + 1][rl] = v.y;
            As[k4 + 2][rl] = v.z; As[k4 + 3][rl] = v.w;
        }
        // load B tile: 128 cols x 16 k (rows of W, permuted column mapping)
        #pragma unroll
        for (int q0 = 0; q0 < 2; q0++) {
            int q  = tid + q0 * 256;
            int nl = q >> 2;
            int k4 = (q & 3) * 4;
            int n  = n0 + nl;
            int p  = n & 511;
            int orig = ((p >> 6) & 3) * 128 + ((p >> 8) & 1) * 64 + (p & 63);
            const float* bp = W + ((long long)((n >> 9) * 512 + orig)) * 256 + k0 + k4;
            float4 v = *(const float4*)bp;
            Bs[k4 + 0][nl] = v.x; Bs[k4 + 1][nl] = v.y;
            Bs[k4 + 2][nl] = v.z; Bs[k4 + 3][nl] = v.w;
        }
        __syncthreads();
        #pragma unroll
        for (int k = 0; k < 16; k++) {
            float4 a0 = *(const float4*)&As[k][ty * 8];
            float4 a1 = *(const float4*)&As[k][ty * 8 + 4];
            float4 b0 = *(const float4*)&Bs[k][tx * 8];
            float4 b1 = *(const float4*)&Bs[k][tx * 8 + 4];
            float av[8] = {a0.x, a0.y, a0.z, a0.w, a1.x, a1.y, a1.z, a1.w};
            float bv[8] = {b0.x, b0.y, b0.z, b0.w, b1.x, b1.y, b1.z, b1.w};
            #pragma unroll
            for (int i = 0; i < 8; i++)
                #pragma unroll
                for (int j = 0; j < 8; j++)
                    acc[i][j] = fmaf(av[i], bv[j], acc[i][j]);
        }
        __syncthreads();
    }

    // biases (per output column)
    float bsum[8];
    #pragma unroll
    for (int j = 0; j < 8; j++) {
        int n = n0 + tx * 8 + j;
        int p = n & 511;
        int orig = ((p >> 6) & 3) * 128 + ((p >> 8) & 1) * 64 + (p & 63);
        int row = (n >> 9) * 512 + orig;
        bsum[j] = bia[row] + bib[row];
    }
    #pragma unroll
    for (int i = 0; i < 8; i++) {
        int m = m0 + ty * 8 + i;
        int s = m >> 6, b = m & 63;
        long long ob = (((long long)d * S_STEPS + s) * 64 + b) * 512 + (n0 & 511) + tx * 8;
        float4 o0 = make_float4(acc[i][0] + bsum[0], acc[i][1] + bsum[1],
                                acc[i][2] + bsum[2], acc[i][3] + bsum[3]);
        float4 o1 = make_float4(acc[i][4] + bsum[4], acc[i][5] + bsum[5],
                                acc[i][6] + bsum[6], acc[i][7] + bsum[7]);
        *(float4*)(outp + ob)     = o0;
        *(float4*)(outp + ob + 4) = o1;
    }
}

// ---------------- recurrent scan ----------------
// 128 blocks: (dir d, batch-pair bg, half r). Cluster of 2 = the two halves.
// Block r owns gate rows orig = t*128 + r*64 + jj  (permuted index l = t*64+jj, p = r*256+l)
// and updates h/c units j in [r*64, r*64+64). h halves exchanged via DSMEM each step.
__global__ void __launch_bounds__(256, 1) __cluster_dims__(2, 1, 1)
recur_kernel(const float* __restrict__ Whh, int is_time)
{
    __shared__ __align__(16) float hbuf[2][2][128];  // [ping][batch][h]
    __shared__ float gbuf[2][256];
    __shared__ float cbuf[2][64];

    const int blk  = blockIdx.x;
    const int r    = blk & 1;
    const int pair = blk >> 1;
    const int d    = pair >> 5;
    const int bg   = pair & 31;
    const int l    = threadIdx.x;          // 0..255 : local gate row
    const int tg   = l >> 6;
    const int jj   = l & 63;
    const int orig = tg * 128 + r * 64 + jj;

    // weights for this gate row -> registers
    float w[128];
    {
        const float* wr = Whh + ((long long)d * 512 + orig) * 128;
        #pragma unroll
        for (int k = 0; k < 128; k += 4) {
            float4 v = *(const float4*)(wr + k);
            w[k] = v.x; w[k + 1] = v.y; w[k + 2] = v.z; w[k + 3] = v.w;
        }
    }

    if (l < 128) {
        hbuf[0][0][l] = 0.f; hbuf[0][1][l] = 0.f;
        hbuf[1][0][l] = 0.f; hbuf[1][1][l] = 0.f;
        cbuf[l >> 6][l & 63] = 0.f;
    }
    __syncthreads();
    cluster_sync_();   // peer's remote writes must not race our init

    const int b0 = bg * 2;
    const float* pbase = g_proj + (((long long)d * S_STEPS) * 64 + b0) * 512 + r * 256 + l;
    const long long sstride = 64 * 512;
    float xc0 = pbase[0];
    float xc1 = pbase[512];

    const uint32_t h_local  = smem_u32(&hbuf[0][0][0]);
    const uint32_t h_remote = mapa_rank(h_local, (uint32_t)(r ^ 1));

    for (int s = 0; s < S_STEPS; ++s) {
        const int cur = s & 1, nxt = cur ^ 1;
        float acc0 = xc0, acc1 = xc1;
        if (s + 1 < S_STEPS) {               // prefetch next step's preactivations
            const float* pn = pbase + (long long)(s + 1) * sstride;
            xc0 = __ldg(pn);
            xc1 = __ldg(pn + 512);
        }
        const float4* h0 = (const float4*)&hbuf[cur][0][0];
        const float4* h1 = (const float4*)&hbuf[cur][1][0];
        #pragma unroll
        for (int k4 = 0; k4 < 32; k4++) {
            float4 a  = h0[k4];
            float4 bq = h1[k4];
            acc0 = fmaf(w[4 * k4 + 0], a.x, acc0);
            acc0 = fmaf(w[4 * k4 + 1], a.y, acc0);
            acc0 = fmaf(w[4 * k4 + 2], a.z, acc0);
            acc0 = fmaf(w[4 * k4 + 3], a.w, acc0);
            acc1 = fmaf(w[4 * k4 + 0], bq.x, acc1);
            acc1 = fmaf(w[4 * k4 + 1], bq.y, acc1);
            acc1 = fmaf(w[4 * k4 + 2], bq.z, acc1);
            acc1 = fmaf(w[4 * k4 + 3], bq.w, acc1);
        }
        gbuf[0][l] = acc0;
        gbuf[1][l] = acc1;
        __syncthreads();
        if (l < 128) {
            const int bb = l >> 6, j = l & 63;
            float gi = gbuf[bb][j];
            float gf = gbuf[bb][64 + j];
            float gg = gbuf[bb][128 + j];
            float go = gbuf[bb][192 + j];
            float c  = cbuf[bb][j];
            float c2 = sigmf_(gf) * c + sigmf_(gi) * tanhf(gg);
            float h2 = sigmf_(go) * tanhf(c2);
            cbuf[bb][j] = c2;
            const int hj = r * 64 + j;
            hbuf[nxt][bb][hj] = h2;
            st_cluster_f32(h_remote + (uint32_t)(((nxt * 2 + bb) * 128 + hj) * 4), h2);
            if (is_time) {
                g_tout[(((long long)s) * 64 + b0 + bb) * 256 + d * 128 + hj] = h2;
            } else if (s == S_STEPS - 1) {
                g_pout[(long long)(b0 + bb) * 256 + d * 128 + hj] = h2;
            }
        }
        cluster_sync_();   // release h-half writes, acquire peer's
    }
}

// ---------------- output GEMM ----------------
__global__ void __launch_bounds__(128)
out_gemm_kernel(const float* __restrict__ Wo, const float* __restrict__ bo,
                float* __restrict__ out)
{
    __shared__ float po[256];
    const int b = blockIdx.x, tid = threadIdx.x;
    po[tid]       = g_pout[b * 256 + tid];
    po[tid + 128] = g_pout[b * 256 + 128 + tid];
    __syncthreads();
    if (tid < NO) {
        float acc = bo[tid];
        const float* wr = Wo + tid * 256;
        #pragma unroll 8
        for (int k = 0; k < 256; k += 4) {
            float4 v = *(const float4*)(wr + k);
            acc = fmaf(v.x, po[k],     acc);
            acc = fmaf(v.y, po[k + 1], acc);
            acc = fmaf(v.z, po[k + 2], acc);
            acc = fmaf(v.w, po[k + 3], acc);
        }
        out[b * NO + tid] = acc;
    }
}

// ---------------- launch ----------------
extern "C" void kernel_launch(void* const* d_in, const int* in_sizes, int n_in,
                              void* d_out, int out_size)
{
    const float* x     = (const float*)d_in[0];
    const float* Wt_ih = (const float*)d_in[1];
    const float* Wt_hh = (const float*)d_in[2];
    const float* bt_ih = (const float*)d_in[3];
    const float* bt_hh = (const float*)d_in[4];
    const float* Wp_ih = (const float*)d_in[5];
    const float* Wp_hh = (const float*)d_in[6];
    const float* bp_ih = (const float*)d_in[7];
    const float* bp_hh = (const float*)d_in[8];
    const float* Wo    = (const float*)d_in[9];
    const float* bo    = (const float*)d_in[10];
    float* out = (float*)d_out;

    dim3 ggrid(8, 1024);  // N/128 x M/128

    // 1) time input projection: xproj = x @ Wt_ih^T + bt_ih + bt_hh  (permuted gate layout)
    proj_gemm_kernel<<<ggrid, 256>>>(x, 524288LL, 256LL, Wt_ih, bt_ih, bt_hh, 0);
    // 2) time recurrence over 2048 steps -> g_tout
    recur_kernel<<<128, 256>>>(Wt_hh, 1);
    // 3) pitch input projection: pproj = tout @ Wp_ih^T + bp_ih + bp_hh (overwrites g_proj)
    proj_gemm_kernel<<<ggrid, 256>>>(nullptr, 256LL, 16384LL, Wp_ih, bp_ih, bp_hh, 1);
    // 4) pitch recurrence -> g_pout (final h only)
    recur_kernel<<<128, 256>>>(Wp_hh, 0);
    // 5) final projection [64,256] @ [256,88]^T + bo
    out_gemm_kernel<<<64, 128>>>(Wo, bo, out);
}

// round 9
// speedup vs baseline: 1.2442x; 1.2442x over previous
#include <cuda_runtime.h>
#include <cuda_bf16.h>
#include <cstdint>
#include <math.h>

// Problem constants
#define S_STEPS 2048   // T*P
#define NB      64     // batch
#define NI      256    // input
#define NH      128    // hidden
#define NG      512    // 4*H
#define NO      88     // output
#define MTOT    (S_STEPS * NB)   // 131072 GEMM rows

// Scratch (static __device__ — allocation APIs are forbidden)
__device__ float g_proj[(size_t)2 * S_STEPS * NB * NG];          // 512 MB
__device__ float g_tout[(size_t)S_STEPS * NB * 256];             // 128 MB
__device__ float g_pout[NB * 256];
__device__ __nv_bfloat16 g_Ah[(size_t)MTOT * 256];               // 64 MB
__device__ __nv_bfloat16 g_Al[(size_t)MTOT * 256];               // 64 MB
__device__ __nv_bfloat16 g_Bh[1024 * 256];
__device__ __nv_bfloat16 g_Bl[1024 * 256];
__device__ float g_bias[1024];

// ---------------- helpers ----------------
__device__ __forceinline__ uint32_t smem_u32(const void* p) {
    uint32_t a;
    asm("{ .reg .u64 t; cvta.to.shared.u64 t, %1; cvt.u32.u64 %0, t; }" : "=r"(a) : "l"(p));
    return a;
}
__device__ __forceinline__ uint32_t mapa_rank(uint32_t a, uint32_t rk) {
    uint32_t r;
    asm("mapa.shared::cluster.u32 %0, %1, %2;" : "=r"(r) : "r"(a), "r"(rk));
    return r;
}
__device__ __forceinline__ void st_cluster_f32(uint32_t a, float v) {
    asm volatile("st.shared::cluster.f32 [%0], %1;" :: "r"(a), "f"(v) : "memory");
}
__device__ __forceinline__ void cluster_sync_() {
    asm volatile("barrier.cluster.arrive.aligned;" ::: "memory");
    asm volatile("barrier.cluster.wait.aligned;" ::: "memory");
}
__device__ __forceinline__ float fsig(float x) {
    float e, r;
    asm("ex2.approx.ftz.f32 %0, %1;" : "=f"(e) : "f"(-1.4426950408889634f * x));
    asm("rcp.approx.ftz.f32 %0, %1;" : "=f"(r) : "f"(1.0f + e));
    return r;
}
__device__ __forceinline__ float ftanh_(float x) {
    float e, r;
    asm("ex2.approx.ftz.f32 %0, %1;" : "=f"(e) : "f"(2.8853900817779268f * x));
    asm("rcp.approx.ftz.f32 %0, %1;" : "=f"(r) : "f"(1.0f + e));
    return fmaf(-2.0f, r, 1.0f);   // tanh(x) = 1 - 2/(1+e^{2x})
}
__device__ __forceinline__ void mma16816(float* c, const uint32_t* a, const uint32_t* b) {
    asm volatile(
        "mma.sync.aligned.m16n8k16.row.col.f32.bf16.bf16.f32 "
        "{%0,%1,%2,%3}, {%4,%5,%6,%7}, {%8,%9}, {%0,%1,%2,%3};"
        : "+f"(c[0]), "+f"(c[1]), "+f"(c[2]), "+f"(c[3])
        : "r"(a[0]), "r"(a[1]), "r"(a[2]), "r"(a[3]), "r"(b[0]), "r"(b[1]));
}

// ---------------- conversion: fp32 A (strided) -> bf16 hi/lo [m][k] ----------------
__global__ void __launch_bounds__(256)
conv_a_kernel(const float* __restrict__ Aext, long long sbB, long long sbS, int internal)
{
    const float* A = internal ? (const float*)g_tout : Aext;
    size_t idx = ((size_t)blockIdx.x * 256 + threadIdx.x) * 8;
    int m = (int)(idx >> 8), k = (int)(idx & 255);
    const float* src = A + (size_t)(m & 63) * sbB + (size_t)(m >> 6) * sbS + k;
    float4 v0 = *(const float4*)src;
    float4 v1 = *(const float4*)(src + 4);
    float f[8] = {v0.x, v0.y, v0.z, v0.w, v1.x, v1.y, v1.z, v1.w};
    union { __nv_bfloat16 b[8]; uint4 u; } hi, lo;
    #pragma unroll
    for (int i = 0; i < 8; i++) {
        hi.b[i] = __float2bfloat16(f[i]);
        lo.b[i] = __float2bfloat16(f[i] - __bfloat162float(hi.b[i]));
    }
    *(uint4*)&g_Ah[idx] = hi.u;
    *(uint4*)&g_Al[idx] = lo.u;
}

// ---------------- conversion: W -> permuted bf16 hi/lo + fused bias ----------------
__global__ void __launch_bounds__(256)
conv_w_kernel(const float* __restrict__ W, const float* __restrict__ bia,
              const float* __restrict__ bib)
{
    size_t idx = ((size_t)blockIdx.x * 256 + threadIdx.x) * 8;
    int n = (int)(idx >> 8), k = (int)(idx & 255);
    int p = n & 511, d = n >> 9;
    int orig = ((p >> 6) & 3) * 128 + ((p >> 8) & 1) * 64 + (p & 63);
    int row = d * 512 + orig;
    const float* src = W + (size_t)row * 256 + k;
    float4 v0 = *(const float4*)src;
    float4 v1 = *(const float4*)(src + 4);
    float f[8] = {v0.x, v0.y, v0.z, v0.w, v1.x, v1.y, v1.z, v1.w};
    union { __nv_bfloat16 b[8]; uint4 u; } hi, lo;
    #pragma unroll
    for (int i = 0; i < 8; i++) {
        hi.b[i] = __float2bfloat16(f[i]);
        lo.b[i] = __float2bfloat16(f[i] - __bfloat162float(hi.b[i]));
    }
    *(uint4*)&g_Bh[idx] = hi.u;
    *(uint4*)&g_Bl[idx] = lo.u;
    if (k == 0) g_bias[n] = bia[row] + bib[row];
}

// ---------------- tensor-core projection GEMM (split-bf16, 3 terms) ----------------
// C[m][n] = sum_k A[m][k]*B[n][k] + bias[n]; out to g_proj[d][s][b][p] (p permuted).
// CTA tile 128x128, K-chunk 32, 8 warps as 4(m) x 2(n), warp tile 32x64.
__global__ void __launch_bounds__(256)
mma_gemm_kernel()
{
    __shared__ __align__(16) __nv_bfloat16 sm[4][128][40];  // Ah, Al, Bh, Bl; stride 40 halves

    const int tid = threadIdx.x;
    const int m0 = blockIdx.y * 128;
    const int n0 = blockIdx.x * 128;
    const int d  = blockIdx.x >> 2;

    const int lane = tid & 31, wid = tid >> 5;
    const int wm = wid >> 1, wn = wid & 1;
    const int fr = lane >> 2, fq = lane & 3;

    float c[2][8][4];
    #pragma unroll
    for (int i = 0; i < 2; i++)
        #pragma unroll
        for (int j = 0; j < 8; j++)
            #pragma unroll
            for (int q = 0; q < 4; q++) c[i][j][q] = 0.0f;

    // gmem load assignment: thread -> (row, 16-element half of the 32-wide chunk)
    // Each thread loads/stores TWO uint4 (16 bf16) per buffer. 256 thr * 16 = 4096 = full tile.
    const int lrow = tid >> 1, lpart = (tid & 1) * 16;
    const __nv_bfloat16* pAh = g_Ah + (size_t)(m0 + lrow) * 256 + lpart;
    const __nv_bfloat16* pAl = g_Al + (size_t)(m0 + lrow) * 256 + lpart;
    const __nv_bfloat16* pBh = g_Bh + (size_t)(n0 + lrow) * 256 + lpart;
    const __nv_bfloat16* pBl = g_Bl + (size_t)(n0 + lrow) * 256 + lpart;

    uint4 ra0 = *(const uint4*)pAh, ra1 = *(const uint4*)(pAh + 8);
    uint4 rb0 = *(const uint4*)pAl, rb1 = *(const uint4*)(pAl + 8);
    uint4 rc0 = *(const uint4*)pBh, rc1 = *(const uint4*)(pBh + 8);
    uint4 rd0 = *(const uint4*)pBl, rd1 = *(const uint4*)(pBl + 8);

    for (int ch = 0; ch < 8; ch++) {
        *(uint4*)&sm[0][lrow][lpart]     = ra0;
        *(uint4*)&sm[0][lrow][lpart + 8] = ra1;
        *(uint4*)&sm[1][lrow][lpart]     = rb0;
        *(uint4*)&sm[1][lrow][lpart + 8] = rb1;
        *(uint4*)&sm[2][lrow][lpart]     = rc0;
        *(uint4*)&sm[2][lrow][lpart + 8] = rc1;
        *(uint4*)&sm[3][lrow][lpart]     = rd0;
        *(uint4*)&sm[3][lrow][lpart + 8] = rd1;
        __syncthreads();
        if (ch < 7) {
            pAh += 32; pAl += 32; pBh += 32; pBl += 32;
            ra0 = *(const uint4*)pAh; ra1 = *(const uint4*)(pAh + 8);
            rb0 = *(const uint4*)pAl; rb1 = *(const uint4*)(pAl + 8);
            rc0 = *(const uint4*)pBh; rc1 = *(const uint4*)(pBh + 8);
            rd0 = *(const uint4*)pBl; rd1 = *(const uint4*)(pBl + 8);
        }
        #pragma unroll
        for (int ks = 0; ks < 32; ks += 16) {
            uint32_t ah[2][4], al[2][4];
            #pragma unroll
            for (int mt = 0; mt < 2; mt++) {
                int rbase = wm * 32 + mt * 16;
                int col = ks + fq * 2;
                ah[mt][0] = *(const uint32_t*)&sm[0][rbase + fr][col];
                ah[mt][1] = *(const uint32_t*)&sm[0][rbase + 8 + fr][col];
                ah[mt][2] = *(const uint32_t*)&sm[0][rbase + fr][col + 8];
                ah[mt][3] = *(const uint32_t*)&sm[0][rbase + 8 + fr][col + 8];
                al[mt][0] = *(const uint32_t*)&sm[1][rbase + fr][col];
                al[mt][1] = *(const uint32_t*)&sm[1][rbase + 8 + fr][col];
                al[mt][2] = *(const uint32_t*)&sm[1][rbase + fr][col + 8];
                al[mt][3] = *(const uint32_t*)&sm[1][rbase + 8 + fr][col + 8];
            }
            #pragma unroll
            for (int nt = 0; nt < 8; nt++) {
                int nr = wn * 64 + nt * 8 + fr;
                int col = ks + fq * 2;
                uint32_t bh[2], bl[2];
                bh[0] = *(const uint32_t*)&sm[2][nr][col];
                bh[1] = *(const uint32_t*)&sm[2][nr][col + 8];
                bl[0] = *(const uint32_t*)&sm[3][nr][col];
                bl[1] = *(const uint32_t*)&sm[3][nr][col + 8];
                #pragma unroll
                for (int mt = 0; mt < 2; mt++) {
                    mma16816(c[mt][nt], ah[mt], bh);   // hi*hi
                    mma16816(c[mt][nt], ah[mt], bl);   // hi*lo
                    mma16816(c[mt][nt], al[mt], bh);   // lo*hi
                }
            }
        }
        __syncthreads();
    }

    // epilogue: bias + permuted-layout store to g_proj
    #pragma unroll
    for (int nt = 0; nt < 8; nt++) {
        int n = n0 + wn * 64 + nt * 8 + fq * 2;
        float b0 = g_bias[n], b1 = g_bias[n + 1];
        int pcol = n & 511;
        #pragma unroll
        for (int mt = 0; mt < 2; mt++) {
            int m1 = m0 + wm * 32 + mt * 16 + fr;
            int m2 = m1 + 8;
            size_t o1 = (((size_t)d * S_STEPS + (m1 >> 6)) * 64 + (m1 & 63)) * 512 + pcol;
            size_t o2 = (((size_t)d * S_STEPS + (m2 >> 6)) * 64 + (m2 & 63)) * 512 + pcol;
            float2 w1 = make_float2(c[mt][nt][0] + b0, c[mt][nt][1] + b1);
            float2 w2 = make_float2(c[mt][nt][2] + b0, c[mt][nt][3] + b1);
            *(float2*)(g_proj + o1) = w1;
            *(float2*)(g_proj + o2) = w2;
        }
    }
}

// ---------------- recurrent scan (round-3 proven structure) ----------------
// 128 blocks: (dir d, batch-pair bg, half r). Cluster of 2 = the two halves.
// Block r owns gate rows orig = t*128 + r*64 + jj (permuted index p = r*256 + t*64 + jj)
// and updates h/c units j in [r*64, r*64+64). h halves exchanged via DSMEM each step.
__global__ void __launch_bounds__(256, 1) __cluster_dims__(2, 1, 1)
recur_kernel(const float* __restrict__ Whh, int is_time)
{
    __shared__ __align__(16) float hbuf[2][2][128];  // [ping][batch][h]
    __shared__ float gbuf[2][256];
    __shared__ float cbuf[2][64];

    const int blk  = blockIdx.x;
    const int r    = blk & 1;
    const int pair = blk >> 1;
    const int d    = pair >> 5;
    const int bg   = pair & 31;
    const int l    = threadIdx.x;          // 0..255 : local gate row
    const int tg   = l >> 6;
    const int jj   = l & 63;
    const int orig = tg * 128 + r * 64 + jj;

    // weights for this gate row -> registers
    float w[128];
    {
        const float* wr = Whh + ((long long)d * 512 + orig) * 128;
        #pragma unroll
        for (int k = 0; k < 128; k += 4) {
            float4 v = *(const float4*)(wr + k);
            w[k] = v.x; w[k + 1] = v.y; w[k + 2] = v.z; w[k + 3] = v.w;
        }
    }

    if (l < 128) {
        hbuf[0][0][l] = 0.f; hbuf[0][1][l] = 0.f;
        hbuf[1][0][l] = 0.f; hbuf[1][1][l] = 0.f;
        cbuf[l >> 6][l & 63] = 0.f;
    }
    __syncthreads();
    cluster_sync_();   // peer's remote writes must not race our init

    const int b0 = bg * 2;
    const float* pbase = g_proj + (((long long)d * S_STEPS) * 64 + b0) * 512 + r * 256 + l;
    const long long sstride = 64 * 512;
    float xc0 = pbase[0];
    float xc1 = pbase[512];

    const uint32_t h_local  = smem_u32(&hbuf[0][0][0]);
    const uint32_t h_remote = mapa_rank(h_local, (uint32_t)(r ^ 1));

    for (int s = 0; s < S_STEPS; ++s) {
        const int cur = s & 1, nxt = cur ^ 1;
        float acc0 = xc0, acc1 = xc1;
        if (s + 1 < S_STEPS) {               // prefetch next step's preactivations
            const float* pn = pbase + (long long)(s + 1) * sstride;
            xc0 = __ldg(pn);
            xc1 = __ldg(pn + 512);
        }
        const float4* h0 = (const float4*)&hbuf[cur][0][0];
        const float4* h1 = (const float4*)&hbuf[cur][1][0];
        #pragma unroll
        for (int k4 = 0; k4 < 32; k4++) {
            float4 a  = h0[k4];
            float4 bq = h1[k4];
            acc0 = fmaf(w[4 * k4 + 0], a.x, acc0);
            acc0 = fmaf(w[4 * k4 + 1], a.y, acc0);
            acc0 = fmaf(w[4 * k4 + 2], a.z, acc0);
            acc0 = fmaf(w[4 * k4 + 3], a.w, acc0);
            acc1 = fmaf(w[4 * k4 + 0], bq.x, acc1);
            acc1 = fmaf(w[4 * k4 + 1], bq.y, acc1);
            acc1 = fmaf(w[4 * k4 + 2], bq.z, acc1);
            acc1 = fmaf(w[4 * k4 + 3], bq.w, acc1);
        }
        gbuf[0][l] = acc0;
        gbuf[1][l] = acc1;
        __syncthreads();
        if (l < 128) {
            const int bb = l >> 6, j = l & 63;
            float gi = gbuf[bb][j];
            float gf = gbuf[bb][64 + j];
            float gg = gbuf[bb][128 + j];
            float go = gbuf[bb][192 + j];
            float cc = cbuf[bb][j];
            float c2 = fsig(gf) * cc + fsig(gi) * ftanh_(gg);
            float h2 = fsig(go) * ftanh_(c2);
            cbuf[bb][j] = c2;
            const int hj = r * 64 + j;
            hbuf[nxt][bb][hj] = h2;
            st_cluster_f32(h_remote + (uint32_t)(((nxt * 2 + bb) * 128 + hj) * 4), h2);
            if (is_time) {
                g_tout[(((long long)s) * 64 + b0 + bb) * 256 + d * 128 + hj] = h2;
            } else if (s == S_STEPS - 1) {
                g_pout[(long long)(b0 + bb) * 256 + d * 128 + hj] = h2;
            }
        }
        cluster_sync_();   // release h-half writes, acquire peer's
    }
}

// ---------------- output GEMM ----------------
__global__ void __launch_bounds__(128)
out_gemm_kernel(const float* __restrict__ Wo, const float* __restrict__ bo,
                float* __restrict__ out)
{
    __shared__ float po[256];
    const int b = blockIdx.x, tid = threadIdx.x;
    po[tid]       = g_pout[b * 256 + tid];
    po[tid + 128] = g_pout[b * 256 + 128 + tid];
    __syncthreads();
    if (tid < NO) {
        float acc = bo[tid];
        const float* wr = Wo + tid * 256;
        #pragma unroll 8
        for (int k = 0; k < 256; k += 4) {
            float4 v = *(const float4*)(wr + k);
            acc = fmaf(v.x, po[k],     acc);
            acc = fmaf(v.y, po[k + 1], acc);
            acc = fmaf(v.z, po[k + 2], acc);
            acc = fmaf(v.w, po[k + 3], acc);
        }
        out[b * NO + tid] = acc;
    }
}

// ---------------- launch ----------------
extern "C" void kernel_launch(void* const* d_in, const int* in_sizes, int n_in,
                              void* d_out, int out_size)
{
    const float* x     = (const float*)d_in[0];
    const float* Wt_ih = (const float*)d_in[1];
    const float* Wt_hh = (const float*)d_in[2];
    const float* bt_ih = (const float*)d_in[3];
    const float* bt_hh = (const float*)d_in[4];
    const float* Wp_ih = (const float*)d_in[5];
    const float* Wp_hh = (const float*)d_in[6];
    const float* bp_ih = (const float*)d_in[7];
    const float* bp_hh = (const float*)d_in[8];
    const float* Wo    = (const float*)d_in[9];
    const float* bo    = (const float*)d_in[10];
    float* out = (float*)d_out;

    dim3 ggrid(8, 1024);               // N/128 x M/128
    const int convBlocks = MTOT * 256 / 8 / 256;   // 16384

    // time phase
    conv_a_kernel<<<convBlocks, 256>>>(x, 524288LL, 256LL, 0);
    conv_w_kernel<<<128, 256>>>(Wt_ih, bt_ih, bt_hh);
    mma_gemm_kernel<<<ggrid, 256>>>();
    recur_kernel<<<128, 256>>>(Wt_hh, 1);
    // pitch phase
    conv_a_kernel<<<convBlocks, 256>>>(nullptr, 256LL, 16384LL, 1);
    conv_w_kernel<<<128, 256>>>(Wp_ih, bp_ih, bp_hh);
    mma_gemm_kernel<<<ggrid, 256>>>();
    recur_kernel<<<128, 256>>>(Wp_hh, 0);
    // final projection
    out_gemm_kernel<<<64, 128>>>(Wo, bo, out);
}